// round 15
// baseline (speedup 1.0000x reference)
#include <cuda_runtime.h>

#define BB 256
#define TT 256
#define CC 512
#define LL 64
#define SS 129              // 2L+1 extended states
#define NSYM 65             // [blank, l0..l63]
#define RWE 68              // emit row stride (floats, 16B multiple)
#define NCONSB 32           // consumer blocks (8 warps each -> 256 consumers)
#define LOG2E 1.4426950408889634f
#define LN2   0.6931471805599453f
#define EZ_EMPTY (-100000)

// Device globals (zero-init). g_emit rewritten fully every launch.
__device__ __align__(16) float g_emit[(size_t)BB * TT * RWE];   // ~17.8 MB -> L2
__device__ int   g_flag[BB * TT];   // row ready flags: value == launch token
__device__ float g_nll[BB];
__device__ int   g_done;            // ticket counter, reset by winner
__device__ int   g_epoch;           // launch token - 1, bumped by winner

__device__ __forceinline__ float exp2i_pm(int d) {
    d = max(d, -127); d = min(d, 127);
    return __uint_as_float((unsigned)(127 + d) << 23);
}
__device__ __forceinline__ int ld_acq_g(const int* p) {
    int v;
    asm volatile("ld.acquire.gpu.global.b32 %0, [%1];" : "=r"(v) : "l"(p) : "memory");
    return v;
}
__device__ __forceinline__ void st_rel_g(int* p, int v) {
    asm volatile("st.release.gpu.global.b32 [%0], %1;" :: "l"(p), "r"(v) : "memory");
}

// ---------------------------------------------------------------------------
// Grid-role-split kernel.
//   blocks [NCONSB, NCONSB+8192): producers. pid = blk-NCONSB; batch = pid&255,
//     chunk = pid>>8; warp w handles row t = chunk*8+w. Softmax row -> g_emit,
//     then release-store token to g_flag. Never waits on consumers.
//   blocks [0, NCONSB): consumers. warp w = batch blk*8+w. CTC recursion
//     (linear domain, per-lane pow2 scaling), rows polled via acquire loads.
// ---------------------------------------------------------------------------
__global__ void __launch_bounds__(256, 4) k_split(const float* __restrict__ logits,
                                                  const int*   __restrict__ labels,
                                                  const int*   __restrict__ lab_len,
                                                  const int*   __restrict__ log_len,
                                                  float* __restrict__ out) {
    int tid  = threadIdx.x;
    int warp = tid >> 5;
    int lane = tid & 31;
    int token = *((volatile int*)&g_epoch) + 1;   // per-launch token (stable)

    if (blockIdx.x >= NCONSB) {
        // =================== PRODUCER (1 warp = 1 row) ===================
        int pid   = blockIdx.x - NCONSB;
        int b     = pid & (BB - 1);
        int chunk = pid >> 8;
        int t     = chunk * 8 + warp;

        const float* rp = logits + ((size_t)b * TT + t) * CC;
        const float4* r4 = reinterpret_cast<const float4*>(rp);
        float4 v0 = r4[lane], v1 = r4[lane + 32], v2 = r4[lane + 64], v3 = r4[lane + 96];

        float ssum =
            exp2f(v0.x*LOG2E)+exp2f(v0.y*LOG2E)+exp2f(v0.z*LOG2E)+exp2f(v0.w*LOG2E)+
            exp2f(v1.x*LOG2E)+exp2f(v1.y*LOG2E)+exp2f(v1.z*LOG2E)+exp2f(v1.w*LOG2E)+
            exp2f(v2.x*LOG2E)+exp2f(v2.y*LOG2E)+exp2f(v2.z*LOG2E)+exp2f(v2.w*LOG2E)+
            exp2f(v3.x*LOG2E)+exp2f(v3.y*LOG2E)+exp2f(v3.z*LOG2E)+exp2f(v3.w*LOG2E);
        #pragma unroll
        for (int o = 16; o; o >>= 1) ssum += __shfl_xor_sync(0xffffffffu, ssum, o);
        float inv = __fdividef(1.0f, ssum);

        float* orow = g_emit + ((size_t)b * TT + t) * RWE;
        const int* lb = labels + b * LL;
        #pragma unroll
        for (int j = lane; j < NSYM; j += 32) {
            int cls = j ? __ldg(&lb[j - 1]) : (CC - 1);
            orow[j] = exp2f(rp[cls] * LOG2E) * inv;     // rp[cls] hits L1
        }
        __syncwarp();
        if (lane == 0) st_rel_g(&g_flag[b * TT + t], token);
    } else {
        // =================== CONSUMER (1 warp = 1 batch) ===================
        int b  = blockIdx.x * 8 + warp;
        int s0 = lane * 5;
        const int* lb = labels + b * LL;
        const float* ebase = g_emit + (size_t)b * TT * RWE;
        int* flg = &g_flag[b * TT];

        int   idx[5];
        float skipf[5];
        #pragma unroll
        for (int k = 0; k < 5; ++k) {
            int s = s0 + k;
            int ks = s >> 1;
            if ((s & 1) && s < SS) {
                idx[k]   = 1 + ks;
                skipf[k] = (s >= 3 && __ldg(&lb[ks]) != __ldg(&lb[ks - 1])) ? 1.f : 0.f;
            } else {
                idx[k]   = 0;
                skipf[k] = 0.f;
            }
        }

        int tend = log_len[b] - 1;
        int send = 2 * lab_len[b];

        // t = 0
        while (ld_acq_g(&flg[0]) != token) __nanosleep(100);
        float a[5];
        a[0] = (s0 == 0) ? ebase[idx[0]] : 0.f;
        a[1] = (s0 == 0) ? ebase[idx[1]] : 0.f;
        a[2] = 0.f; a[3] = 0.f; a[4] = 0.f;
        int   ez = (s0 == 0) ? 0 : EZ_EMPTY;
        float si;

        float cf0 = 0.f, cf1 = 0.f;
        int   cez0 = 0, cez1 = 0;
        if (tend == 0) {
            #pragma unroll
            for (int k = 0; k < 5; ++k) {
                if (s0 + k == send)     { cf0 = a[k]; cez0 = ez; }
                if (s0 + k == send - 1) { cf1 = a[k]; cez1 = ez; }
            }
        }

        #define RENORM_EXCHANGE() do {                                             \
            float w_ = fmaxf(fmaxf(fmaxf(a[0], a[1]), fmaxf(a[2], a[3])), a[4]);   \
            unsigned wu_ = __float_as_uint(w_);                                     \
            int ex_, eznew_;                                                        \
            if (wu_ != 0u) { ex_ = (int)((wu_ >> 23) & 255) - 127; eznew_ = ez + ex_; } \
            else           { ex_ = 0; eznew_ = EZ_EMPTY; }                          \
            int en_ = __shfl_up_sync(0xffffffffu, eznew_, 1);                       \
            if (lane == 0) en_ = EZ_EMPTY;                                          \
            int mz_ = max(eznew_, en_);                                             \
            float cs_ = exp2i_pm(-ex_ + ((eznew_ - mz_ < -127) ? -127 : (eznew_ - mz_))); \
            if (eznew_ == EZ_EMPTY) cs_ = 0.f;                                      \
            a[0] *= cs_; a[1] *= cs_; a[2] *= cs_; a[3] *= cs_; a[4] *= cs_;        \
            ez = (mz_ == EZ_EMPTY) ? EZ_EMPTY : mz_;                                \
            si = (lane == 0) ? 0.f : exp2i_pm((en_ - ez < -127) ? -127 : (en_ - ez)); \
            if (lane == 0) si = 0.f;                                                \
        } while (0)

        #define STEPR(E_, T_) do {                                                  \
            float p4 = __shfl_up_sync(0xffffffffu, a[4], 1) * si;                   \
            float p3 = __shfl_up_sync(0xffffffffu, a[3], 1) * si;                   \
            float n0 = fmaf(skipf[0], p3,   a[0] + p4)   * (E_)[0];                 \
            float n1 = fmaf(skipf[1], p4,   a[1] + a[0]) * (E_)[1];                 \
            float n2 = fmaf(skipf[2], a[0], a[2] + a[1]) * (E_)[2];                 \
            float n3 = fmaf(skipf[3], a[1], a[3] + a[2]) * (E_)[3];                 \
            float n4 = fmaf(skipf[4], a[2], a[4] + a[3]) * (E_)[4];                 \
            a[0] = n0; a[1] = n1; a[2] = n2; a[3] = n3; a[4] = n4;                  \
            if (__builtin_expect((T_) == tend, 0)) {                                \
                if (s0     == send)     { cf0 = a[0]; cez0 = ez; }                  \
                if (s0 + 1 == send)     { cf0 = a[1]; cez0 = ez; }                  \
                if (s0 + 2 == send)     { cf0 = a[2]; cez0 = ez; }                  \
                if (s0 + 3 == send)     { cf0 = a[3]; cez0 = ez; }                  \
                if (s0 + 4 == send)     { cf0 = a[4]; cez0 = ez; }                  \
                if (s0     == send - 1) { cf1 = a[0]; cez1 = ez; }                  \
                if (s0 + 1 == send - 1) { cf1 = a[1]; cez1 = ez; }                  \
                if (s0 + 2 == send - 1) { cf1 = a[2]; cez1 = ez; }                  \
                if (s0 + 3 == send - 1) { cf1 = a[3]; cez1 = ez; }                  \
                if (s0 + 4 == send - 1) { cf1 = a[4]; cez1 = ez; }                  \
            }                                                                       \
        } while (0)

        RENORM_EXCHANGE();   // si for t = 1..4

        for (int g = 0; g < 63; ++g) {
            int t0 = 1 + 4 * g;
            // poll 4 flags (same sector) with acquire; backoff on miss
            for (;;) {
                int rA = ld_acq_g(&flg[t0]);
                int rB = ld_acq_g(&flg[t0 + 1]);
                int rC = ld_acq_g(&flg[t0 + 2]);
                int rD = ld_acq_g(&flg[t0 + 3]);
                if (rA == token && rB == token && rC == token && rD == token) break;
                __nanosleep(100);
            }
            const float* pA = ebase + (size_t)t0 * RWE;
            const float* pB = pA + RWE;
            const float* pC = pB + RWE;
            const float* pD = pC + RWE;
            float eA[5], eB[5], eC[5], eD[5];
            #pragma unroll
            for (int k = 0; k < 5; ++k) {
                eA[k] = pA[idx[k]]; eB[k] = pB[idx[k]];
                eC[k] = pC[idx[k]]; eD[k] = pD[idx[k]];
            }
            STEPR(eA, t0); STEPR(eB, t0 + 1); STEPR(eC, t0 + 2); STEPR(eD, t0 + 3);
            RENORM_EXCHANGE();
        }
        #pragma unroll
        for (int t = 253; t <= 255; ++t) {
            while (ld_acq_g(&flg[t]) != token) __nanosleep(100);
            const float* p = ebase + (size_t)t * RWE;
            float eT[5];
            #pragma unroll
            for (int k = 0; k < 5; ++k) eT[k] = p[idx[k]];
            STEPR(eT, t);
        }

        float v0 = (cf0 > 0.f) ? (logf(cf0) + (float)cez0 * LN2) : -3.0e38f;
        float v1 = (cf1 > 0.f) ? (logf(cf1) + (float)cez1 * LN2) : -3.0e38f;
        #pragma unroll
        for (int o = 16; o; o >>= 1) {
            v0 = fmaxf(v0, __shfl_xor_sync(0xffffffffu, v0, o));
            v1 = fmaxf(v1, __shfl_xor_sync(0xffffffffu, v1, o));
        }
        int is_last = 0;
        if (lane == 0) {
            float mm = fmaxf(v0, v1);
            g_nll[b] = -(mm + logf(expf(v0 - mm) + expf(v1 - mm)));
            __threadfence();
            is_last = (atomicAdd(&g_done, 1) == BB - 1);
        }
        is_last = __shfl_sync(0xffffffffu, is_last, 0);
        if (is_last) {
            __threadfence();
            // Deterministic fixed-order mean over B.
            float s_ = 0.f;
            #pragma unroll
            for (int i = 0; i < 8; ++i) s_ += __ldcg(&g_nll[lane * 8 + i]);
            #pragma unroll
            for (int o = 16; o; o >>= 1) s_ += __shfl_xor_sync(0xffffffffu, s_, o);
            if (lane == 0) {
                out[0] = s_ * (1.0f / BB);
                g_done = 0;                 // reset ticket for next replay
                atomicAdd(&g_epoch, 1);     // advance launch token
                __threadfence();
            }
        }
    }
}

// ---------------------------------------------------------------------------
extern "C" void kernel_launch(void* const* d_in, const int* in_sizes, int n_in,
                              void* d_out, int out_size) {
    const float* logits  = (const float*)d_in[0];
    const int*   labels  = (const int*)  d_in[1];
    const int*   lab_len = (const int*)  d_in[2];
    const int*   log_len = (const int*)  d_in[3];

    int grid = NCONSB + (BB * TT) / 8;   // 32 consumer + 8192 producer blocks
    k_split<<<grid, 256>>>(logits, labels, lab_len, log_len, (float*)d_out);
}

// round 16
// speedup vs baseline: 2.5831x; 2.5831x over previous
#include <cuda_runtime.h>

#define BB 256
#define TT 256
#define CC 512
#define LL 64
#define SS 129              // 2L+1 extended states
#define NSYM 65             // [blank, l0..l63]
#define RW 68               // ring row width in floats
#define RING 32             // ring depth (rows)
#define NPROD 15            // producer warps per batch
#define LOG2E 1.4426950408889634f
#define LN2   0.6931471805599453f
#define EZ_EMPTY (-100000)

__device__ float g_nll[BB];
__device__ int   g_done;    // zero-init; reset by winner each launch

__device__ __forceinline__ float exp2i_pm(int d) {
    d = max(d, -127); d = min(d, 127);
    return __uint_as_float((unsigned)(127 + d) << 23);
}
__device__ __forceinline__ int ld_acq(const int* p) {
    int v;
    asm volatile("ld.acquire.cta.shared.b32 %0, [%1];"
                 : "=r"(v) : "r"((unsigned)__cvta_generic_to_shared(p)) : "memory");
    return v;
}
__device__ __forceinline__ void st_rel(int* p, int v) {
    asm volatile("st.release.cta.shared.b32 [%0], %1;"
                 :: "r"((unsigned)__cvta_generic_to_shared(p)), "r"(v) : "memory");
}

// ---------------------------------------------------------------------------
// Fused kernel: 1 block = 1 batch element, 512 threads (16 warps), grid 256.
// 2 blocks co-resident per SM (regs capped at 64) -> ~28 warps/SM issuing
// DRAM loads across all 148 SMs, single wave.
// Warps 0-14: producers (softmax rows -> smem ring, 1-row lookahead).
// Warp 15: consumer (CTC recursion, per-lane pow2 scaling, sleep-backoff).
// ---------------------------------------------------------------------------
__global__ void __launch_bounds__(512, 2) k_fused(const float* __restrict__ logits,
                                                  const int*   __restrict__ labels,
                                                  const int*   __restrict__ lab_len,
                                                  const int*   __restrict__ log_len,
                                                  float* __restrict__ out) {
    __shared__ __align__(16) float ring[RING][RW];
    __shared__ int labels_s[LL];
    __shared__ int ready[RING];   // row t written -> value t+1
    __shared__ int consT;         // consumer progress

    int tid  = threadIdx.x;
    int warp = tid >> 5;
    int lane = tid & 31;
    int b    = blockIdx.x;

    if (tid < LL) labels_s[tid] = labels[b * LL + tid];
    if (tid >= 64 && tid < 64 + RING) ready[tid - 64] = 0;
    if (tid == 96) consT = -1;
    __syncthreads();

    if (warp < NPROD) {
        // =================== PRODUCER ===================
        const int* lb = labels_s;
        int t = warp;
        const float* rp = logits + ((size_t)b * TT + t) * CC;
        const float4* r4 = reinterpret_cast<const float4*>(rp);
        float4 c0 = r4[lane], c1 = r4[lane + 32], c2 = r4[lane + 64], c3 = r4[lane + 96];

        while (t < TT) {
            int tn = t + NPROD;
            const float* rpn = logits + ((size_t)b * TT + (tn < TT ? tn : 0)) * CC;
            const float4* r4n = reinterpret_cast<const float4*>(rpn);
            float4 d0 = r4n[lane], d1 = r4n[lane + 32],
                   d2 = r4n[lane + 64], d3 = r4n[lane + 96];

            float ssum =
                exp2f(c0.x*LOG2E)+exp2f(c0.y*LOG2E)+exp2f(c0.z*LOG2E)+exp2f(c0.w*LOG2E)+
                exp2f(c1.x*LOG2E)+exp2f(c1.y*LOG2E)+exp2f(c1.z*LOG2E)+exp2f(c1.w*LOG2E)+
                exp2f(c2.x*LOG2E)+exp2f(c2.y*LOG2E)+exp2f(c2.z*LOG2E)+exp2f(c2.w*LOG2E)+
                exp2f(c3.x*LOG2E)+exp2f(c3.y*LOG2E)+exp2f(c3.z*LOG2E)+exp2f(c3.w*LOG2E);
            #pragma unroll
            for (int o = 16; o; o >>= 1) ssum += __shfl_xor_sync(0xffffffffu, ssum, o);
            float inv = __fdividef(1.0f, ssum);

            if (t >= RING) {
                while (ld_acq(&consT) < t - (RING - 1)) __nanosleep(50);
            }
            int slot = t & (RING - 1);
            float* rrow = &ring[slot][0];
            #pragma unroll
            for (int j = lane; j < NSYM; j += 32) {
                int cls = j ? lb[j - 1] : (CC - 1);
                rrow[j] = exp2f(rp[cls] * LOG2E) * inv;
            }
            __syncwarp();
            if (lane == 0) st_rel(&ready[slot], t + 1);

            c0 = d0; c1 = d1; c2 = d2; c3 = d3;
            rp = rpn; t = tn;
        }
    } else if (warp == NPROD) {
        // =================== CONSUMER ===================
        int s0 = lane * 5;
        const int* lb = labels_s;
        float* rs = &ring[0][0];
        int*  rdy = &ready[0];

        int   idx[5];
        float skipf[5];
        #pragma unroll
        for (int k = 0; k < 5; ++k) {
            int s = s0 + k;
            int ks = s >> 1;
            if ((s & 1) && s < SS) {
                idx[k]   = 1 + ks;
                skipf[k] = (s >= 3 && lb[ks] != lb[ks - 1]) ? 1.f : 0.f;
            } else {
                idx[k]   = 0;
                skipf[k] = 0.f;
            }
        }

        int tend = log_len[b] - 1;
        int send = 2 * lab_len[b];

        while (ld_acq(&rdy[0]) < 1) __nanosleep(60);
        float a[5];
        a[0] = (s0 == 0) ? rs[idx[0]] : 0.f;
        a[1] = (s0 == 0) ? rs[idx[1]] : 0.f;
        a[2] = 0.f; a[3] = 0.f; a[4] = 0.f;
        int   ez = (s0 == 0) ? 0 : EZ_EMPTY;
        float si;

        float cf0 = 0.f, cf1 = 0.f;
        int   cez0 = 0, cez1 = 0;
        if (tend == 0) {
            #pragma unroll
            for (int k = 0; k < 5; ++k) {
                if (s0 + k == send)     { cf0 = a[k]; cez0 = ez; }
                if (s0 + k == send - 1) { cf1 = a[k]; cez1 = ez; }
            }
        }

        #define RENORM_EXCHANGE() do {                                             \
            float w_ = fmaxf(fmaxf(fmaxf(a[0], a[1]), fmaxf(a[2], a[3])), a[4]);   \
            unsigned wu_ = __float_as_uint(w_);                                     \
            int ex_, eznew_;                                                        \
            if (wu_ != 0u) { ex_ = (int)((wu_ >> 23) & 255) - 127; eznew_ = ez + ex_; } \
            else           { ex_ = 0; eznew_ = EZ_EMPTY; }                          \
            int en_ = __shfl_up_sync(0xffffffffu, eznew_, 1);                       \
            if (lane == 0) en_ = EZ_EMPTY;                                          \
            int mz_ = max(eznew_, en_);                                             \
            float cs_ = exp2i_pm(-ex_ + ((eznew_ - mz_ < -127) ? -127 : (eznew_ - mz_))); \
            if (eznew_ == EZ_EMPTY) cs_ = 0.f;                                      \
            a[0] *= cs_; a[1] *= cs_; a[2] *= cs_; a[3] *= cs_; a[4] *= cs_;        \
            ez = (mz_ == EZ_EMPTY) ? EZ_EMPTY : mz_;                                \
            si = (lane == 0) ? 0.f : exp2i_pm((en_ - ez < -127) ? -127 : (en_ - ez)); \
            if (lane == 0) si = 0.f;                                                \
        } while (0)

        #define STEPR(E_, T_) do {                                                  \
            float p4 = __shfl_up_sync(0xffffffffu, a[4], 1) * si;                   \
            float p3 = __shfl_up_sync(0xffffffffu, a[3], 1) * si;                   \
            float n0 = fmaf(skipf[0], p3,   a[0] + p4)   * (E_)[0];                 \
            float n1 = fmaf(skipf[1], p4,   a[1] + a[0]) * (E_)[1];                 \
            float n2 = fmaf(skipf[2], a[0], a[2] + a[1]) * (E_)[2];                 \
            float n3 = fmaf(skipf[3], a[1], a[3] + a[2]) * (E_)[3];                 \
            float n4 = fmaf(skipf[4], a[2], a[4] + a[3]) * (E_)[4];                 \
            a[0] = n0; a[1] = n1; a[2] = n2; a[3] = n3; a[4] = n4;                  \
            if (__builtin_expect((T_) == tend, 0)) {                                \
                if (s0     == send)     { cf0 = a[0]; cez0 = ez; }                  \
                if (s0 + 1 == send)     { cf0 = a[1]; cez0 = ez; }                  \
                if (s0 + 2 == send)     { cf0 = a[2]; cez0 = ez; }                  \
                if (s0 + 3 == send)     { cf0 = a[3]; cez0 = ez; }                  \
                if (s0 + 4 == send)     { cf0 = a[4]; cez0 = ez; }                  \
                if (s0     == send - 1) { cf1 = a[0]; cez1 = ez; }                  \
                if (s0 + 1 == send - 1) { cf1 = a[1]; cez1 = ez; }                  \
                if (s0 + 2 == send - 1) { cf1 = a[2]; cez1 = ez; }                  \
                if (s0 + 3 == send - 1) { cf1 = a[3]; cez1 = ez; }                  \
                if (s0 + 4 == send - 1) { cf1 = a[4]; cez1 = ez; }                  \
            }                                                                       \
        } while (0)

        RENORM_EXCHANGE();   // si for t = 1..4

        for (int g = 0; g < 63; ++g) {
            int t0 = 1 + 4 * g;
            int sA = t0 & 31, sB = (t0 + 1) & 31, sC = (t0 + 2) & 31, sD = (t0 + 3) & 31;
            for (;;) {
                int rA = ld_acq(&rdy[sA]);
                int rB = ld_acq(&rdy[sB]);
                int rC = ld_acq(&rdy[sC]);
                int rD = ld_acq(&rdy[sD]);
                if (rA > t0 && rB > t0 + 1 && rC > t0 + 2 && rD > t0 + 3) break;
                __nanosleep(60);
            }
            const float* pA = rs + sA * RW;
            const float* pB = rs + sB * RW;
            const float* pC = rs + sC * RW;
            const float* pD = rs + sD * RW;
            float eA[5], eB[5], eC[5], eD[5];
            #pragma unroll
            for (int k = 0; k < 5; ++k) {
                eA[k] = pA[idx[k]]; eB[k] = pB[idx[k]];
                eC[k] = pC[idx[k]]; eD[k] = pD[idx[k]];
            }
            STEPR(eA, t0); STEPR(eB, t0 + 1); STEPR(eC, t0 + 2); STEPR(eD, t0 + 3);
            RENORM_EXCHANGE();
            st_rel(&consT, t0 + 3);
        }
        #pragma unroll
        for (int t = 253; t <= 255; ++t) {
            int sl = t & 31;
            while (ld_acq(&rdy[sl]) < t + 1) __nanosleep(60);
            const float* p = rs + sl * RW;
            float eT[5];
            #pragma unroll
            for (int k = 0; k < 5; ++k) eT[k] = p[idx[k]];
            STEPR(eT, t);
        }
        st_rel(&consT, 255);

        float v0 = (cf0 > 0.f) ? (logf(cf0) + (float)cez0 * LN2) : -3.0e38f;
        float v1 = (cf1 > 0.f) ? (logf(cf1) + (float)cez1 * LN2) : -3.0e38f;
        #pragma unroll
        for (int o = 16; o; o >>= 1) {
            v0 = fmaxf(v0, __shfl_xor_sync(0xffffffffu, v0, o));
            v1 = fmaxf(v1, __shfl_xor_sync(0xffffffffu, v1, o));
        }
        int is_last = 0;
        if (lane == 0) {
            float mm = fmaxf(v0, v1);
            g_nll[b] = -(mm + logf(expf(v0 - mm) + expf(v1 - mm)));
            __threadfence();
            is_last = (atomicAdd(&g_done, 1) == BB - 1);
        }
        is_last = __shfl_sync(0xffffffffu, is_last, 0);
        if (is_last) {
            __threadfence();
            float s_ = 0.f;
            #pragma unroll
            for (int i = 0; i < 8; ++i) s_ += __ldcg(&g_nll[lane * 8 + i]);
            #pragma unroll
            for (int o = 16; o; o >>= 1) s_ += __shfl_xor_sync(0xffffffffu, s_, o);
            if (lane == 0) {
                out[0] = s_ * (1.0f / BB);
                g_done = 0;
                __threadfence();
            }
        }
    }
}

// ---------------------------------------------------------------------------
extern "C" void kernel_launch(void* const* d_in, const int* in_sizes, int n_in,
                              void* d_out, int out_size) {
    const float* logits  = (const float*)d_in[0];
    const int*   labels  = (const int*)  d_in[1];
    const int*   lab_len = (const int*)  d_in[2];
    const int*   log_len = (const int*)  d_in[3];

    k_fused<<<BB, 512>>>(logits, labels, lab_len, log_len, (float*)d_out);
}

// round 17
// speedup vs baseline: 3.0779x; 1.1916x over previous
#include <cuda_runtime.h>

#define BB 256
#define TT 256
#define CC 512
#define LL 64
#define SS 129              // 2L+1 extended states
#define NSYM 65             // [blank, l0..l63]
#define RW 68               // ring row width in floats
#define RING 64             // ring depth (rows)
#define NPROD 13            // producer warps per batch
#define LOG2E 1.4426950408889634f
#define LN2   0.6931471805599453f
#define EZ_EMPTY (-100000)

__device__ float g_nll[BB];
__device__ int   g_done;    // zero-init; reset by winner each launch

__device__ __forceinline__ float exp2i_pm(int d) {
    d = max(d, -127); d = min(d, 127);
    return __uint_as_float((unsigned)(127 + d) << 23);
}
__device__ __forceinline__ int ld_acq(const int* p) {
    int v;
    asm volatile("ld.acquire.cta.shared.b32 %0, [%1];"
                 : "=r"(v) : "r"((unsigned)__cvta_generic_to_shared(p)) : "memory");
    return v;
}
__device__ __forceinline__ void st_rel(int* p, int v) {
    asm volatile("st.release.cta.shared.b32 [%0], %1;"
                 :: "r"((unsigned)__cvta_generic_to_shared(p)), "r"(v) : "memory");
}

// ---------------------------------------------------------------------------
// Fused kernel: 1 block = 1 batch element, 448 threads (14 warps), grid 256.
// __launch_bounds__(448,2): reg cap 73 (>= the 72 the producer needs - no
// spill), 2 blocks/SM -> 28 warps/SM, single wave on 148 SMs.
// Warps 0-12: producers (softmax rows -> 64-row smem ring, 1-row lookahead).
// Warp 13: consumer (CTC recursion, per-lane pow2 scaling, sleep-backoff).
// ---------------------------------------------------------------------------
__global__ void __launch_bounds__(448, 2) k_fused(const float* __restrict__ logits,
                                                  const int*   __restrict__ labels,
                                                  const int*   __restrict__ lab_len,
                                                  const int*   __restrict__ log_len,
                                                  float* __restrict__ out) {
    __shared__ __align__(16) float ring[RING][RW];
    __shared__ int labels_s[LL];
    __shared__ int ready[RING];   // row t written -> value t+1
    __shared__ int consT;         // consumer progress

    int tid  = threadIdx.x;
    int warp = tid >> 5;
    int lane = tid & 31;
    int b    = blockIdx.x;

    if (tid < LL) labels_s[tid] = labels[b * LL + tid];
    if (tid >= 64 && tid < 64 + RING) ready[tid - 64] = 0;
    if (tid == 128 + 32) consT = -1;
    __syncthreads();

    if (warp < NPROD) {
        // =================== PRODUCER ===================
        const int* lb = labels_s;
        int t = warp;
        const float* rp = logits + ((size_t)b * TT + t) * CC;
        const float4* r4 = reinterpret_cast<const float4*>(rp);
        float4 c0 = r4[lane], c1 = r4[lane + 32], c2 = r4[lane + 64], c3 = r4[lane + 96];

        while (t < TT) {
            int tn = t + NPROD;
            const float* rpn = logits + ((size_t)b * TT + (tn < TT ? tn : 0)) * CC;
            const float4* r4n = reinterpret_cast<const float4*>(rpn);
            float4 d0 = r4n[lane], d1 = r4n[lane + 32],
                   d2 = r4n[lane + 64], d3 = r4n[lane + 96];

            float ssum =
                exp2f(c0.x*LOG2E)+exp2f(c0.y*LOG2E)+exp2f(c0.z*LOG2E)+exp2f(c0.w*LOG2E)+
                exp2f(c1.x*LOG2E)+exp2f(c1.y*LOG2E)+exp2f(c1.z*LOG2E)+exp2f(c1.w*LOG2E)+
                exp2f(c2.x*LOG2E)+exp2f(c2.y*LOG2E)+exp2f(c2.z*LOG2E)+exp2f(c2.w*LOG2E)+
                exp2f(c3.x*LOG2E)+exp2f(c3.y*LOG2E)+exp2f(c3.z*LOG2E)+exp2f(c3.w*LOG2E);
            #pragma unroll
            for (int o = 16; o; o >>= 1) ssum += __shfl_xor_sync(0xffffffffu, ssum, o);
            float inv = __fdividef(1.0f, ssum);

            if (t >= RING) {
                while (ld_acq(&consT) < t - (RING - 1)) __nanosleep(40);
            }
            int slot = t & (RING - 1);
            float* rrow = &ring[slot][0];
            #pragma unroll
            for (int j = lane; j < NSYM; j += 32) {
                int cls = j ? lb[j - 1] : (CC - 1);
                rrow[j] = exp2f(rp[cls] * LOG2E) * inv;
            }
            __syncwarp();
            if (lane == 0) st_rel(&ready[slot], t + 1);

            c0 = d0; c1 = d1; c2 = d2; c3 = d3;
            rp = rpn; t = tn;
        }
    } else if (warp == NPROD) {
        // =================== CONSUMER ===================
        int s0 = lane * 5;
        const int* lb = labels_s;
        float* rs = &ring[0][0];
        int*  rdy = &ready[0];

        int   idx[5];
        float skipf[5];
        #pragma unroll
        for (int k = 0; k < 5; ++k) {
            int s = s0 + k;
            int ks = s >> 1;
            if ((s & 1) && s < SS) {
                idx[k]   = 1 + ks;
                skipf[k] = (s >= 3 && lb[ks] != lb[ks - 1]) ? 1.f : 0.f;
            } else {
                idx[k]   = 0;
                skipf[k] = 0.f;
            }
        }

        int tend = log_len[b] - 1;
        int send = 2 * lab_len[b];

        while (ld_acq(&rdy[0]) < 1) __nanosleep(40);
        float a[5];
        a[0] = (s0 == 0) ? rs[idx[0]] : 0.f;
        a[1] = (s0 == 0) ? rs[idx[1]] : 0.f;
        a[2] = 0.f; a[3] = 0.f; a[4] = 0.f;
        int   ez = (s0 == 0) ? 0 : EZ_EMPTY;
        float si;

        float cf0 = 0.f, cf1 = 0.f;
        int   cez0 = 0, cez1 = 0;
        if (tend == 0) {
            #pragma unroll
            for (int k = 0; k < 5; ++k) {
                if (s0 + k == send)     { cf0 = a[k]; cez0 = ez; }
                if (s0 + k == send - 1) { cf1 = a[k]; cez1 = ez; }
            }
        }

        #define RENORM_EXCHANGE() do {                                             \
            float w_ = fmaxf(fmaxf(fmaxf(a[0], a[1]), fmaxf(a[2], a[3])), a[4]);   \
            unsigned wu_ = __float_as_uint(w_);                                     \
            int ex_, eznew_;                                                        \
            if (wu_ != 0u) { ex_ = (int)((wu_ >> 23) & 255) - 127; eznew_ = ez + ex_; } \
            else           { ex_ = 0; eznew_ = EZ_EMPTY; }                          \
            int en_ = __shfl_up_sync(0xffffffffu, eznew_, 1);                       \
            if (lane == 0) en_ = EZ_EMPTY;                                          \
            int mz_ = max(eznew_, en_);                                             \
            float cs_ = exp2i_pm(-ex_ + ((eznew_ - mz_ < -127) ? -127 : (eznew_ - mz_))); \
            if (eznew_ == EZ_EMPTY) cs_ = 0.f;                                      \
            a[0] *= cs_; a[1] *= cs_; a[2] *= cs_; a[3] *= cs_; a[4] *= cs_;        \
            ez = (mz_ == EZ_EMPTY) ? EZ_EMPTY : mz_;                                \
            si = (lane == 0) ? 0.f : exp2i_pm((en_ - ez < -127) ? -127 : (en_ - ez)); \
            if (lane == 0) si = 0.f;                                                \
        } while (0)

        #define STEPR(E_, T_) do {                                                  \
            float p4 = __shfl_up_sync(0xffffffffu, a[4], 1) * si;                   \
            float p3 = __shfl_up_sync(0xffffffffu, a[3], 1) * si;                   \
            float n0 = fmaf(skipf[0], p3,   a[0] + p4)   * (E_)[0];                 \
            float n1 = fmaf(skipf[1], p4,   a[1] + a[0]) * (E_)[1];                 \
            float n2 = fmaf(skipf[2], a[0], a[2] + a[1]) * (E_)[2];                 \
            float n3 = fmaf(skipf[3], a[1], a[3] + a[2]) * (E_)[3];                 \
            float n4 = fmaf(skipf[4], a[2], a[4] + a[3]) * (E_)[4];                 \
            a[0] = n0; a[1] = n1; a[2] = n2; a[3] = n3; a[4] = n4;                  \
            if (__builtin_expect((T_) == tend, 0)) {                                \
                if (s0     == send)     { cf0 = a[0]; cez0 = ez; }                  \
                if (s0 + 1 == send)     { cf0 = a[1]; cez0 = ez; }                  \
                if (s0 + 2 == send)     { cf0 = a[2]; cez0 = ez; }                  \
                if (s0 + 3 == send)     { cf0 = a[3]; cez0 = ez; }                  \
                if (s0 + 4 == send)     { cf0 = a[4]; cez0 = ez; }                  \
                if (s0     == send - 1) { cf1 = a[0]; cez1 = ez; }                  \
                if (s0 + 1 == send - 1) { cf1 = a[1]; cez1 = ez; }                  \
                if (s0 + 2 == send - 1) { cf1 = a[2]; cez1 = ez; }                  \
                if (s0 + 3 == send - 1) { cf1 = a[3]; cez1 = ez; }                  \
                if (s0 + 4 == send - 1) { cf1 = a[4]; cez1 = ez; }                  \
            }                                                                       \
        } while (0)

        RENORM_EXCHANGE();   // si for t = 1..4

        for (int g = 0; g < 63; ++g) {
            int t0 = 1 + 4 * g;
            int sA = t0 & (RING - 1), sB = (t0 + 1) & (RING - 1),
                sC = (t0 + 2) & (RING - 1), sD = (t0 + 3) & (RING - 1);
            for (;;) {
                int rA = ld_acq(&rdy[sA]);
                int rB = ld_acq(&rdy[sB]);
                int rC = ld_acq(&rdy[sC]);
                int rD = ld_acq(&rdy[sD]);
                if (rA > t0 && rB > t0 + 1 && rC > t0 + 2 && rD > t0 + 3) break;
                __nanosleep(40);
            }
            const float* pA = rs + sA * RW;
            const float* pB = rs + sB * RW;
            const float* pC = rs + sC * RW;
            const float* pD = rs + sD * RW;
            float eA[5], eB[5], eC[5], eD[5];
            #pragma unroll
            for (int k = 0; k < 5; ++k) {
                eA[k] = pA[idx[k]]; eB[k] = pB[idx[k]];
                eC[k] = pC[idx[k]]; eD[k] = pD[idx[k]];
            }
            STEPR(eA, t0); STEPR(eB, t0 + 1); STEPR(eC, t0 + 2); STEPR(eD, t0 + 3);
            RENORM_EXCHANGE();
            st_rel(&consT, t0 + 3);
        }
        #pragma unroll
        for (int t = 253; t <= 255; ++t) {
            int sl = t & (RING - 1);
            while (ld_acq(&rdy[sl]) < t + 1) __nanosleep(40);
            const float* p = rs + sl * RW;
            float eT[5];
            #pragma unroll
            for (int k = 0; k < 5; ++k) eT[k] = p[idx[k]];
            STEPR(eT, t);
        }
        st_rel(&consT, 255);

        float v0 = (cf0 > 0.f) ? (logf(cf0) + (float)cez0 * LN2) : -3.0e38f;
        float v1 = (cf1 > 0.f) ? (logf(cf1) + (float)cez1 * LN2) : -3.0e38f;
        #pragma unroll
        for (int o = 16; o; o >>= 1) {
            v0 = fmaxf(v0, __shfl_xor_sync(0xffffffffu, v0, o));
            v1 = fmaxf(v1, __shfl_xor_sync(0xffffffffu, v1, o));
        }
        int is_last = 0;
        if (lane == 0) {
            float mm = fmaxf(v0, v1);
            g_nll[b] = -(mm + logf(expf(v0 - mm) + expf(v1 - mm)));
            __threadfence();
            is_last = (atomicAdd(&g_done, 1) == BB - 1);
        }
        is_last = __shfl_sync(0xffffffffu, is_last, 0);
        if (is_last) {
            __threadfence();
            float s_ = 0.f;
            #pragma unroll
            for (int i = 0; i < 8; ++i) s_ += __ldcg(&g_nll[lane * 8 + i]);
            #pragma unroll
            for (int o = 16; o; o >>= 1) s_ += __shfl_xor_sync(0xffffffffu, s_, o);
            if (lane == 0) {
                out[0] = s_ * (1.0f / BB);
                g_done = 0;
                __threadfence();
            }
        }
    }
}

// ---------------------------------------------------------------------------
extern "C" void kernel_launch(void* const* d_in, const int* in_sizes, int n_in,
                              void* d_out, int out_size) {
    const float* logits  = (const float*)d_in[0];
    const int*   labels  = (const int*)  d_in[1];
    const int*   lab_len = (const int*)  d_in[2];
    const int*   log_len = (const int*)  d_in[3];

    k_fused<<<BB, 448>>>(logits, labels, lab_len, log_len, (float*)d_out);
}